// round 6
// baseline (speedup 1.0000x reference)
#include <cuda_runtime.h>
#include <cuda_bf16.h>
#include <cstdint>

// GIB_Layer: M=50000 queries, K=32 support, 4 kinds x G=8 gaussian basis fns,
// masked mean over K, then (32 x 16) mixing matmul. REACH=1, EPS=1e-8.
//
// R5: grid-stride warps, TWO queries per iteration (pair m, m+num_warps) so
// both two-hop gather chains (idx LDG -> point LDG) are in flight together:
// doubles MLP, halves exposed L2 latency. Query-invariant setup (unified
// per-lane coefficients incl. divisions, 16-reg lambda slice with 1/K folded
// in) hoisted out of the loop. Ballot-compacted exp (~8% density), pure
// shuffle 32x16 epilogue. No shared memory, no __syncthreads.

#define GIB_K     32
#define GIB_OBS   16
#define GIB_F     32          // 4*G features
#define GIB_EPS   1e-8f
#define WPB       4           // warps per block
#define QPW       8           // target queries per warp
#define LOG2E     1.4426950408889634f

__device__ __forceinline__ float fast_exp2(float x) {
    float y;
    asm("ex2.approx.ftz.f32 %0, %1;" : "=f"(y) : "f"(x));
    return y;
}

__global__ __launch_bounds__(WPB * 32)
void gib_layer_kernel(const float* __restrict__ points,
                      const float* __restrict__ q_coords,
                      const int*   __restrict__ support_idxs,
                      const float* __restrict__ cy_radius,
                      const float* __restrict__ disk_radius,
                      const float* __restrict__ disk_width,
                      const float* __restrict__ cone_radius,
                      const float* __restrict__ cone_inc,
                      const float* __restrict__ ellip_radii,
                      const float* __restrict__ lambdas,
                      float* __restrict__ out,
                      int M)
{
    const int lane      = threadIdx.x & 31;
    const int warp_glb  = (blockIdx.x * WPB) + (threadIdx.x >> 5);
    const int num_warps = gridDim.x * WPB;

    // ---- per-lane weight coefficients (query-invariant):
    // lane -> (kind = lane>>3, g = lane&7); unified base-2 exponent
    //   a*x2 + b*y2 + c*z2 + d*rz + k0,  rz = sqrt(x2+y2+EPS)*z
    const int kind = lane >> 3;
    const int g    = lane & 7;
    float a, b, c, d, k0;
    {
        const float NHL = -0.5f * LOG2E;
        if (kind == 0) {                  // cylinder
            float r = cy_radius[g];
            float P = NHL / (r * r + GIB_EPS);
            a = P; b = P; c = 0.f; d = 0.f; k0 = 0.f;
        } else if (kind == 1) {           // cone
            float r   = cone_radius[g];
            float inc = cone_inc[g];
            float Q = NHL / (r * r + GIB_EPS);
            a = Q; b = Q; c = Q * inc * inc; d = -2.f * Q * inc; k0 = Q * GIB_EPS;
        } else if (kind == 2) {           // disk
            float dr = disk_radius[g], dw = disk_width[g];
            float Dr = NHL / (dr * dr + GIB_EPS);
            float Dw = NHL / (dw * dw + GIB_EPS);
            a = Dr; b = Dr; c = Dw; d = 0.f; k0 = 0.f;
        } else {                          // ellipsoid
            float ra = ellip_radii[g * 3 + 0];
            float rb = ellip_radii[g * 3 + 1];
            float rc = ellip_radii[g * 3 + 2];
            a = NHL / (ra * ra + GIB_EPS);
            b = NHL / (rb * rb + GIB_EPS);
            c = NHL / (rc * rc + GIB_EPS);
            d = 0.f; k0 = 0.f;
        }
    }

    // ---- per-lane lambda slice (query-invariant), 1/K folded in.
    // lane l handles output o=l&15 over features f=(l&16)+j, j=0..15.
    const int o_idx = lane & 15;
    const int f0    = lane & 16;
    float lam[16];
    #pragma unroll
    for (int j = 0; j < 16; j++)
        lam[j] = lambdas[(f0 + j) * GIB_OBS + o_idx] * (1.0f / (float)GIB_K);

    // ================= per-query helpers (macro-free, inlined twice) =======
    auto gather = [&](int m, float& x2, float& y2, float& z2, float& rz) {
        const int pi  = support_idxs[m * GIB_K + lane];
        const int odd = pi & 1;
        const float2 v2 = *reinterpret_cast<const float2*>(points + 3 * pi + odd);
        const float  vs = points[3 * pi + (odd ? 0 : 2)];
        const float qx = q_coords[3 * m + 0];
        const float qy = q_coords[3 * m + 1];
        const float qz = q_coords[3 * m + 2];
        const float x = (odd ? vs   : v2.x) - qx;
        const float y = (odd ? v2.x : v2.y) - qy;
        const float z = (odd ? v2.y : vs  ) - qz;
        x2 = x * x; y2 = y * y; z2 = z * z;
        rz = sqrtf(x2 + y2 + GIB_EPS) * z;
    };

    auto accumulate = [&](float x2, float y2, float z2, float rz) -> float {
        const float d2 = x2 + y2 + z2;
        unsigned bal = __ballot_sync(0xffffffffu, d2 <= 1.0f);   // REACH^2=1
        float acc = 0.f;
        while (bal) {
            const int j = __ffs(bal) - 1;
            bal &= bal - 1;
            const float bx2 = __shfl_sync(0xffffffffu, x2, j);
            const float by2 = __shfl_sync(0xffffffffu, y2, j);
            const float bz2 = __shfl_sync(0xffffffffu, z2, j);
            const float brz = __shfl_sync(0xffffffffu, rz, j);
            const float arg = fmaf(a, bx2, fmaf(b, by2, fmaf(c, bz2, fmaf(d, brz, k0))));
            acc += fast_exp2(arg);
        }
        return acc;   // un-normalized; 1/K folded into lam
    };

    auto epilogue = [&](int m, float acc) {
        float oacc = 0.f;
        #pragma unroll
        for (int j = 0; j < 16; j++) {
            const float bf = __shfl_sync(0xffffffffu, acc, f0 | j);
            oacc = fmaf(bf, lam[j], oacc);
        }
        oacc += __shfl_xor_sync(0xffffffffu, oacc, 16);
        if (lane < GIB_OBS)
            out[m * GIB_OBS + lane] = oacc;
    };
    // =======================================================================

    int m = warp_glb;
    // paired iterations: both gather chains in flight before any consumption
    for (; m + num_warps < M; m += 2 * num_warps) {
        const int m2 = m + num_warps;
        float x2a, y2a, z2a, rza, x2b, y2b, z2b, rzb;
        gather(m,  x2a, y2a, z2a, rza);
        gather(m2, x2b, y2b, z2b, rzb);
        const float accA = accumulate(x2a, y2a, z2a, rza);
        const float accB = accumulate(x2b, y2b, z2b, rzb);
        epilogue(m,  accA);
        epilogue(m2, accB);
    }
    if (m < M) {
        float x2a, y2a, z2a, rza;
        gather(m, x2a, y2a, z2a, rza);
        epilogue(m, accumulate(x2a, y2a, z2a, rza));
    }
}

extern "C" void kernel_launch(void* const* d_in, const int* in_sizes, int n_in,
                              void* d_out, int out_size)
{
    const float* points       = (const float*)d_in[0];
    const float* q_coords     = (const float*)d_in[1];
    const int*   support_idxs = (const int*)  d_in[2];
    const float* cy_radius    = (const float*)d_in[3];
    const float* disk_radius  = (const float*)d_in[4];
    const float* disk_width   = (const float*)d_in[5];
    const float* cone_radius  = (const float*)d_in[6];
    const float* cone_inc     = (const float*)d_in[7];
    const float* ellip_radii  = (const float*)d_in[8];
    const float* lambdas      = (const float*)d_in[9];
    float* out = (float*)d_out;

    const int M = in_sizes[1] / 3;        // q_coords is (M, 3)
    int blocks = (M + (WPB * QPW) - 1) / (WPB * QPW);
    if (blocks < 1) blocks = 1;

    gib_layer_kernel<<<blocks, WPB * 32>>>(points, q_coords, support_idxs,
                                           cy_radius, disk_radius, disk_width,
                                           cone_radius, cone_inc, ellip_radii,
                                           lambdas, out, M);
}

// round 7
// speedup vs baseline: 1.1651x; 1.1651x over previous
#include <cuda_runtime.h>
#include <cuda_bf16.h>
#include <cstdint>

// GIB_Layer: M=50000 queries, K=32 support, 4 kinds x G=8 gaussian basis fns,
// masked mean over K, then (32 x 16) mixing matmul. REACH=1, EPS=1e-8.
//
// R7: R4 structure (single query per loop iteration — consecutive grid-stride
// iterations already overlap via the scoreboard; explicit pairing only bloats
// registers, see R5 post-mortem), but with QPW=4 so the grid supplies ~84
// warps/SM (occupancy ceiling) instead of 42. Query-invariant setup hoisted:
// unified per-lane coefficients (incl. divisions) and a 16-reg lambda slice
// with 1/K folded in. Parity-aligned LDG.64+LDG.32 gather, ballot-compacted
// exp (~8% density), pure-shuffle 32x16 epilogue. No shared mem, no syncs.

#define GIB_K     32
#define GIB_OBS   16
#define GIB_F     32          // 4*G features
#define GIB_EPS   1e-8f
#define WPB       8           // warps per block
#define QPW       4           // target queries per warp
#define LOG2E     1.4426950408889634f

__device__ __forceinline__ float fast_exp2(float x) {
    float y;
    asm("ex2.approx.ftz.f32 %0, %1;" : "=f"(y) : "f"(x));
    return y;
}

__global__ __launch_bounds__(WPB * 32)
void gib_layer_kernel(const float* __restrict__ points,
                      const float* __restrict__ q_coords,
                      const int*   __restrict__ support_idxs,
                      const float* __restrict__ cy_radius,
                      const float* __restrict__ disk_radius,
                      const float* __restrict__ disk_width,
                      const float* __restrict__ cone_radius,
                      const float* __restrict__ cone_inc,
                      const float* __restrict__ ellip_radii,
                      const float* __restrict__ lambdas,
                      float* __restrict__ out,
                      int M)
{
    const int lane      = threadIdx.x & 31;
    const int warp_glb  = (blockIdx.x * WPB) + (threadIdx.x >> 5);
    const int num_warps = gridDim.x * WPB;

    // ---- per-lane weight coefficients (query-invariant):
    // lane -> (kind = lane>>3, g = lane&7); unified base-2 exponent
    //   a*x2 + b*y2 + c*z2 + d*rz + k0,  rz = sqrt(x2+y2+EPS)*z
    const int kind = lane >> 3;
    const int g    = lane & 7;
    float a, b, c, d, k0;
    {
        const float NHL = -0.5f * LOG2E;
        if (kind == 0) {                  // cylinder
            float r = cy_radius[g];
            float P = NHL / (r * r + GIB_EPS);
            a = P; b = P; c = 0.f; d = 0.f; k0 = 0.f;
        } else if (kind == 1) {           // cone
            float r   = cone_radius[g];
            float inc = cone_inc[g];
            float Q = NHL / (r * r + GIB_EPS);
            a = Q; b = Q; c = Q * inc * inc; d = -2.f * Q * inc; k0 = Q * GIB_EPS;
        } else if (kind == 2) {           // disk
            float dr = disk_radius[g], dw = disk_width[g];
            float Dr = NHL / (dr * dr + GIB_EPS);
            float Dw = NHL / (dw * dw + GIB_EPS);
            a = Dr; b = Dr; c = Dw; d = 0.f; k0 = 0.f;
        } else {                          // ellipsoid
            float ra = ellip_radii[g * 3 + 0];
            float rb = ellip_radii[g * 3 + 1];
            float rc = ellip_radii[g * 3 + 2];
            a = NHL / (ra * ra + GIB_EPS);
            b = NHL / (rb * rb + GIB_EPS);
            c = NHL / (rc * rc + GIB_EPS);
            d = 0.f; k0 = 0.f;
        }
    }

    // ---- per-lane lambda slice (query-invariant), 1/K folded in.
    // lane l handles output o=l&15 over features f=(l&16)+j, j=0..15.
    const int o_idx = lane & 15;
    const int f0    = lane & 16;
    float lam[16];
    #pragma unroll
    for (int j = 0; j < 16; j++)
        lam[j] = lambdas[(f0 + j) * GIB_OBS + o_idx] * (1.0f / (float)GIB_K);

    // ---- query loop (grid-stride): whole warp shares one m per iteration.
    for (int m = warp_glb; m < M; m += num_warps) {
        const int pi  = support_idxs[m * GIB_K + lane];
        const int odd = pi & 1;
        // pi even: LDG.64 at 12*pi -> (x,y), scalar +8 -> z
        // pi odd:  LDG.64 at 12*pi+4 -> (y,z), scalar +0 -> x
        const float2 v2 = *reinterpret_cast<const float2*>(points + 3 * pi + odd);
        const float  vs = points[3 * pi + (odd ? 0 : 2)];
        const float qx = q_coords[3 * m + 0];
        const float qy = q_coords[3 * m + 1];
        const float qz = q_coords[3 * m + 2];

        const float x = (odd ? vs   : v2.x) - qx;
        const float y = (odd ? v2.x : v2.y) - qy;
        const float z = (odd ? v2.y : vs  ) - qz;

        const float x2 = x * x, y2 = y * y, z2 = z * z;
        const float d2 = x2 + y2 + z2;
        const float rz = sqrtf(x2 + y2 + GIB_EPS) * z;

        unsigned bal = __ballot_sync(0xffffffffu, d2 <= 1.0f);   // REACH^2=1
        float acc = 0.f;
        while (bal) {
            const int j = __ffs(bal) - 1;
            bal &= bal - 1;
            const float bx2 = __shfl_sync(0xffffffffu, x2, j);
            const float by2 = __shfl_sync(0xffffffffu, y2, j);
            const float bz2 = __shfl_sync(0xffffffffu, z2, j);
            const float brz = __shfl_sync(0xffffffffu, rz, j);
            const float arg = fmaf(a, bx2, fmaf(b, by2, fmaf(c, bz2, fmaf(d, brz, k0))));
            acc += fast_exp2(arg);
        }
        // 1/K folded into lam

        // ---- epilogue: out[m, o] = sum_f feat[f] * lambdas[f, o].
        float oacc = 0.f;
        #pragma unroll
        for (int j = 0; j < 16; j++) {
            const float bf = __shfl_sync(0xffffffffu, acc, f0 | j);
            oacc = fmaf(bf, lam[j], oacc);
        }
        oacc += __shfl_xor_sync(0xffffffffu, oacc, 16);

        if (lane < GIB_OBS)
            out[m * GIB_OBS + lane] = oacc;
    }
}

extern "C" void kernel_launch(void* const* d_in, const int* in_sizes, int n_in,
                              void* d_out, int out_size)
{
    const float* points       = (const float*)d_in[0];
    const float* q_coords     = (const float*)d_in[1];
    const int*   support_idxs = (const int*)  d_in[2];
    const float* cy_radius    = (const float*)d_in[3];
    const float* disk_radius  = (const float*)d_in[4];
    const float* disk_width   = (const float*)d_in[5];
    const float* cone_radius  = (const float*)d_in[6];
    const float* cone_inc     = (const float*)d_in[7];
    const float* ellip_radii  = (const float*)d_in[8];
    const float* lambdas      = (const float*)d_in[9];
    float* out = (float*)d_out;

    const int M = in_sizes[1] / 3;        // q_coords is (M, 3)
    int blocks = (M + (WPB * QPW) - 1) / (WPB * QPW);
    if (blocks < 1) blocks = 1;

    gib_layer_kernel<<<blocks, WPB * 32>>>(points, q_coords, support_idxs,
                                           cy_radius, disk_radius, disk_width,
                                           cone_radius, cone_inc, ellip_radii,
                                           lambdas, out, M);
}

// round 8
// speedup vs baseline: 1.1879x; 1.0196x over previous
#include <cuda_runtime.h>
#include <cuda_bf16.h>
#include <cstdint>

// GIB_Layer: M=50000 queries, K=32 support, 4 kinds x G=8 gaussian basis fns,
// masked mean over K, then (32 x 16) mixing matmul. REACH=1, EPS=1e-8.
//
// R8: R4 structure/config (warp per query, QPW=8, WPB=4, 6252 warps) plus
// manual software pipelining: iteration i issues its point gathers, then
// PREFETCHES iteration i+1's support indices and query coords before running
// the data-dependent ballot loop + epilogue. This hides the ~577-cycle idx
// DRAM latency behind current-iteration compute; only the ~250-cycle point
// L2 latency stays exposed. Query-invariant setup hoisted (unified per-lane
// coefficients incl. divisions; 16-reg lambda slice with 1/K folded in).
// Parity-aligned LDG.64+LDG.32 gather, ballot-compacted exp (~8% density),
// pure-shuffle 32x16 epilogue. No shared mem, no syncs.

#define GIB_K     32
#define GIB_OBS   16
#define GIB_F     32          // 4*G features
#define GIB_EPS   1e-8f
#define WPB       4           // warps per block
#define QPW       8           // target queries per warp
#define LOG2E     1.4426950408889634f

__device__ __forceinline__ float fast_exp2(float x) {
    float y;
    asm("ex2.approx.ftz.f32 %0, %1;" : "=f"(y) : "f"(x));
    return y;
}

__global__ __launch_bounds__(WPB * 32)
void gib_layer_kernel(const float* __restrict__ points,
                      const float* __restrict__ q_coords,
                      const int*   __restrict__ support_idxs,
                      const float* __restrict__ cy_radius,
                      const float* __restrict__ disk_radius,
                      const float* __restrict__ disk_width,
                      const float* __restrict__ cone_radius,
                      const float* __restrict__ cone_inc,
                      const float* __restrict__ ellip_radii,
                      const float* __restrict__ lambdas,
                      float* __restrict__ out,
                      int M)
{
    const int lane      = threadIdx.x & 31;
    const int warp_glb  = (blockIdx.x * WPB) + (threadIdx.x >> 5);
    const int num_warps = gridDim.x * WPB;

    // ---- per-lane weight coefficients (query-invariant):
    // lane -> (kind = lane>>3, g = lane&7); unified base-2 exponent
    //   a*x2 + b*y2 + c*z2 + d*rz + k0,  rz = sqrt(x2+y2+EPS)*z
    const int kind = lane >> 3;
    const int g    = lane & 7;
    float a, b, c, d, k0;
    {
        const float NHL = -0.5f * LOG2E;
        if (kind == 0) {                  // cylinder
            float r = cy_radius[g];
            float P = NHL / (r * r + GIB_EPS);
            a = P; b = P; c = 0.f; d = 0.f; k0 = 0.f;
        } else if (kind == 1) {           // cone
            float r   = cone_radius[g];
            float inc = cone_inc[g];
            float Q = NHL / (r * r + GIB_EPS);
            a = Q; b = Q; c = Q * inc * inc; d = -2.f * Q * inc; k0 = Q * GIB_EPS;
        } else if (kind == 2) {           // disk
            float dr = disk_radius[g], dw = disk_width[g];
            float Dr = NHL / (dr * dr + GIB_EPS);
            float Dw = NHL / (dw * dw + GIB_EPS);
            a = Dr; b = Dr; c = Dw; d = 0.f; k0 = 0.f;
        } else {                          // ellipsoid
            float ra = ellip_radii[g * 3 + 0];
            float rb = ellip_radii[g * 3 + 1];
            float rc = ellip_radii[g * 3 + 2];
            a = NHL / (ra * ra + GIB_EPS);
            b = NHL / (rb * rb + GIB_EPS);
            c = NHL / (rc * rc + GIB_EPS);
            d = 0.f; k0 = 0.f;
        }
    }

    // ---- per-lane lambda slice (query-invariant), 1/K folded in.
    // lane l handles output o=l&15 over features f=(l&16)+j, j=0..15.
    const int o_idx = lane & 15;
    const int f0    = lane & 16;
    float lam[16];
    #pragma unroll
    for (int j = 0; j < 16; j++)
        lam[j] = lambdas[(f0 + j) * GIB_OBS + o_idx] * (1.0f / (float)GIB_K);

    // ---- software-pipelined query loop: idx/q for iteration i are already
    // in registers when iteration i starts; i+1's are prefetched before the
    // data-dependent ballot loop.
    int m = warp_glb;
    if (m >= M) return;

    int   pi = support_idxs[m * GIB_K + lane];
    float qx = q_coords[3 * m + 0];
    float qy = q_coords[3 * m + 1];
    float qz = q_coords[3 * m + 2];

    while (true) {
        // issue point gathers for current iteration (parity-aligned)
        const int odd = pi & 1;
        const float2 v2 = *reinterpret_cast<const float2*>(points + 3 * pi + odd);
        const float  vs = points[3 * pi + (odd ? 0 : 2)];

        // prefetch next iteration's idx + query coords (warp-uniform branch)
        const int m2 = m + num_warps;
        const bool has_next = (m2 < M);
        int pi_n = 0; float qxn = 0.f, qyn = 0.f, qzn = 0.f;
        if (has_next) {
            pi_n = support_idxs[m2 * GIB_K + lane];
            qxn  = q_coords[3 * m2 + 0];
            qyn  = q_coords[3 * m2 + 1];
            qzn  = q_coords[3 * m2 + 2];
        }

        const float x = (odd ? vs   : v2.x) - qx;
        const float y = (odd ? v2.x : v2.y) - qy;
        const float z = (odd ? v2.y : vs  ) - qz;

        const float x2 = x * x, y2 = y * y, z2 = z * z;
        const float d2 = x2 + y2 + z2;
        const float rz = sqrtf(x2 + y2 + GIB_EPS) * z;

        unsigned bal = __ballot_sync(0xffffffffu, d2 <= 1.0f);   // REACH^2=1
        float acc = 0.f;
        while (bal) {
            const int j = __ffs(bal) - 1;
            bal &= bal - 1;
            const float bx2 = __shfl_sync(0xffffffffu, x2, j);
            const float by2 = __shfl_sync(0xffffffffu, y2, j);
            const float bz2 = __shfl_sync(0xffffffffu, z2, j);
            const float brz = __shfl_sync(0xffffffffu, rz, j);
            const float arg = fmaf(a, bx2, fmaf(b, by2, fmaf(c, bz2, fmaf(d, brz, k0))));
            acc += fast_exp2(arg);
        }
        // 1/K folded into lam

        // ---- epilogue: out[m, o] = sum_f feat[f] * lambdas[f, o].
        float oacc = 0.f;
        #pragma unroll
        for (int j = 0; j < 16; j++) {
            const float bf = __shfl_sync(0xffffffffu, acc, f0 | j);
            oacc = fmaf(bf, lam[j], oacc);
        }
        oacc += __shfl_xor_sync(0xffffffffu, oacc, 16);

        if (lane < GIB_OBS)
            out[m * GIB_OBS + lane] = oacc;

        if (!has_next) break;
        m = m2; pi = pi_n; qx = qxn; qy = qyn; qz = qzn;
    }
}

extern "C" void kernel_launch(void* const* d_in, const int* in_sizes, int n_in,
                              void* d_out, int out_size)
{
    const float* points       = (const float*)d_in[0];
    const float* q_coords     = (const float*)d_in[1];
    const int*   support_idxs = (const int*)  d_in[2];
    const float* cy_radius    = (const float*)d_in[3];
    const float* disk_radius  = (const float*)d_in[4];
    const float* disk_width   = (const float*)d_in[5];
    const float* cone_radius  = (const float*)d_in[6];
    const float* cone_inc     = (const float*)d_in[7];
    const float* ellip_radii  = (const float*)d_in[8];
    const float* lambdas      = (const float*)d_in[9];
    float* out = (float*)d_out;

    const int M = in_sizes[1] / 3;        // q_coords is (M, 3)
    int blocks = (M + (WPB * QPW) - 1) / (WPB * QPW);
    if (blocks < 1) blocks = 1;

    gib_layer_kernel<<<blocks, WPB * 32>>>(points, q_coords, support_idxs,
                                           cy_radius, disk_radius, disk_width,
                                           cone_radius, cone_inc, ellip_radii,
                                           lambdas, out, M);
}